// round 4
// baseline (speedup 1.0000x reference)
#include <cuda_runtime.h>
#include <cuda_bf16.h>

#define NBLK 2048
#define NTHR 256

// Deterministic per-block partials (no atomics -> bit-stable across graph replays)
__device__ double g_part_ce[NBLK];
__device__ double g_part_tp[NBLK];
__device__ double g_part_nc[NBLK];

struct Acc { float ce; float tp; int nc; };

__device__ __forceinline__ void process_row(
    float4 lo, float4 hi, int t, const float* __restrict__ s_bw, Acc& a)
{
    const float r15 = 1.0f / 1.5f;
    float l0=lo.x, l1=lo.y, l2=lo.z, l3=lo.w;
    float l4=hi.x, l5=hi.y, l6=hi.z, l7=hi.w;

    // max + argmax (first-max semantics; strict >)
    float m = l0; int am = 0;
    if (l1 > m) { m = l1; am = 1; }
    if (l2 > m) { m = l2; am = 2; }
    if (l3 > m) { m = l3; am = 3; }
    if (l4 > m) { m = l4; am = 4; }
    if (l5 > m) { m = l5; am = 5; }
    if (l6 > m) { m = l6; am = 6; }
    if (l7 > m) { m = l7; am = 7; }

    float d0=l0-m, d1=l1-m, d2=l2-m, d3=l3-m;
    float d4=l4-m, d5=l5-m, d6=l6-m, d7=l7-m;

    // softmax @ T=1 (recall term)
    float e0=__expf(d0), e1=__expf(d1), e2=__expf(d2), e3=__expf(d3);
    float e4=__expf(d4), e5=__expf(d5), e6=__expf(d6), e7=__expf(d7);
    float s1  = ((e0+e1)+(e2+e3)) + ((e4+e5)+(e6+e7));
    float s1c = (e0+e1)+e3;

    // log_softmax @ T=1.5 (CE term)
    float z0=d0*r15, z1=d1*r15, z2=d2*r15, z3=d3*r15;
    float z4=d4*r15, z5=d5*r15, z6=d6*r15, z7=d7*r15;
    float f0=__expf(z0), f1=__expf(z1), f2=__expf(z2), f3=__expf(z3);
    float f4=__expf(z4), f5=__expf(z5), f6=__expf(z6), f7=__expf(z7);
    float s2 = ((f0+f1)+(f2+f3)) + ((f4+f5)+(f6+f7));
    float lse = __logf(s2);

    float zsum = ((z0+z1)+(z2+z3)) + ((z4+z5)+(z6+z7));
    float zcs  = (z0+z1)+z3;

    // select z[t] without local-memory spill
    float zt = z0;
    zt = (t==1) ? z1 : zt;
    zt = (t==2) ? z2 : zt;
    zt = (t==3) ? z3 : zt;
    zt = (t==4) ? z4 : zt;
    zt = (t==5) ? z5 : zt;
    zt = (t==6) ? z6 : zt;
    zt = (t==7) ? z7 : zt;

    float sum_lp = zsum - 8.0f * lse;
    float lp_t   = zt   - lse;
    float lp_c   = zcs  - 3.0f * lse;

    bool ct = (t==0) | (t==1) | (t==3);
    // cancer row:  smooth=0.05 -> A=0.05/8, B=0.95, E=0        (sum=1)
    // benign row:  smooth=0.10 -> (0.0125 + 0.9*onehot + 0.0166667*cancer)/1.05
    float Ac = ct ? 0.00625f : 0.0119047619f;
    float Bc = ct ? 0.95f    : 0.8571428571f;
    float Ec = ct ? 0.0f     : 0.0158730159f;

    float ce = -(Ac * sum_lp + Bc * lp_t + Ec * lp_c);
    ce *= s_bw[t];

    bool pc = (am==0) | (am==1) | (am==3);
    float mult = 1.0f;
    if (ct && !pc)       mult = 3.0f;   // FN_MULT
    if ((t==0) && !pc)   mult = 5.0f;   // MEL_FN_MULT (overrides)
    if (ct && (am != t)) mult *= 2.0f;  // hard mining
    ce *= mult;

    a.ce += ce;
    if (ct) { a.tp += __fdividef(s1c, s1); a.nc++; }
}

__global__ __launch_bounds__(NTHR) void mrl_main(
    const float4* __restrict__ L4,          // logits as float4 pairs per row
    const int*    __restrict__ targets,
    const float*  __restrict__ counts,
    int B)
{
    __shared__ float s_bw[8];
    if (threadIdx.x == 0) {
        float w0 = rsqrtf(counts[0] + 1.0f), w1 = rsqrtf(counts[1] + 1.0f);
        float w2 = rsqrtf(counts[2] + 1.0f), w3 = rsqrtf(counts[3] + 1.0f);
        float w4 = rsqrtf(counts[4] + 1.0f), w5 = rsqrtf(counts[5] + 1.0f);
        float w6 = rsqrtf(counts[6] + 1.0f), w7 = rsqrtf(counts[7] + 1.0f);
        float s = ((w0+w1)+(w2+w3)) + ((w4+w5)+(w6+w7));
        float inv = 8.0f / s;
        s_bw[0]=w0*inv; s_bw[1]=w1*inv; s_bw[2]=w2*inv; s_bw[3]=w3*inv;
        s_bw[4]=w4*inv; s_bw[5]=w5*inv; s_bw[6]=w6*inv; s_bw[7]=w7*inv;
    }
    __syncthreads();

    Acc a; a.ce = 0.f; a.tp = 0.f; a.nc = 0;

    const int stride = NBLK * NTHR;
    int r = blockIdx.x * NTHR + threadIdx.x;

    // two rows per iteration: 4 independent float4 loads in flight (MLP 4)
    for (; r + stride < B; r += 2 * stride) {
        int r2 = r + stride;
        const float4* p  = L4 + ((long long)r  << 1);
        const float4* q  = L4 + ((long long)r2 << 1);
        float4 lo0 = __ldg(p);
        float4 hi0 = __ldg(p + 1);
        float4 lo1 = __ldg(q);
        float4 hi1 = __ldg(q + 1);
        int t0 = __ldg(targets + r);
        int t1 = __ldg(targets + r2);
        process_row(lo0, hi0, t0, s_bw, a);
        process_row(lo1, hi1, t1, s_bw, a);
    }
    for (; r < B; r += stride) {
        const float4* p = L4 + ((long long)r << 1);
        float4 lo = __ldg(p);
        float4 hi = __ldg(p + 1);
        int t = __ldg(targets + r);
        process_row(lo, hi, t, s_bw, a);
    }

    float ce_sum = a.ce, tp_sum = a.tp;
    int nc = a.nc;

    // warp reduce
    #pragma unroll
    for (int o = 16; o; o >>= 1) {
        ce_sum += __shfl_down_sync(0xffffffffu, ce_sum, o);
        tp_sum += __shfl_down_sync(0xffffffffu, tp_sum, o);
        nc     += __shfl_down_sync(0xffffffffu, nc,     o);
    }

    __shared__ float sh_ce[NTHR/32], sh_tp[NTHR/32];
    __shared__ int   sh_nc[NTHR/32];
    int wid = threadIdx.x >> 5, lid = threadIdx.x & 31;
    if (lid == 0) { sh_ce[wid] = ce_sum; sh_tp[wid] = tp_sum; sh_nc[wid] = nc; }
    __syncthreads();

    if (threadIdx.x == 0) {
        double c = 0.0, tpd = 0.0; long long n = 0;
        #pragma unroll
        for (int i = 0; i < NTHR/32; i++) { c += (double)sh_ce[i]; tpd += (double)sh_tp[i]; n += sh_nc[i]; }
        g_part_ce[blockIdx.x] = c;
        g_part_tp[blockIdx.x] = tpd;
        g_part_nc[blockIdx.x] = (double)n;
    }
}

__global__ __launch_bounds__(256) void mrl_final(float* __restrict__ out, int B) {
    __shared__ double sc[256], st[256], sn[256];
    double c = 0.0, t = 0.0, n = 0.0;
    for (int i = threadIdx.x; i < NBLK; i += 256) {
        c += g_part_ce[i]; t += g_part_tp[i]; n += g_part_nc[i];
    }
    sc[threadIdx.x] = c; st[threadIdx.x] = t; sn[threadIdx.x] = n;
    __syncthreads();
    #pragma unroll
    for (int o = 128; o; o >>= 1) {
        if (threadIdx.x < o) {
            sc[threadIdx.x] += sc[threadIdx.x + o];
            st[threadIdx.x] += st[threadIdx.x + o];
            sn[threadIdx.x] += sn[threadIdx.x + o];
        }
        __syncthreads();
    }
    if (threadIdx.x == 0) {
        double base_loss = sc[0] / (double)B;
        // tp + fn == count of cancer-target samples
        double soft_recall = st[0] / (sn[0] + 1e-8);
        out[0] = (float)(base_loss + 0.5 * (1.0 - soft_recall));
    }
}

extern "C" void kernel_launch(void* const* d_in, const int* in_sizes, int n_in,
                              void* d_out, int out_size) {
    const float* logits  = (const float*)d_in[0];
    const int*   targets = (const int*)d_in[1];
    const float* counts  = (const float*)d_in[2];
    float* out = (float*)d_out;
    int B = in_sizes[1];   // number of rows (targets element count)

    mrl_main<<<NBLK, NTHR>>>((const float4*)logits, targets, counts, B);
    mrl_final<<<1, 256>>>(out, B);
}

// round 12
// speedup vs baseline: 1.0109x; 1.0109x over previous
#include <cuda_runtime.h>
#include <cuda_bf16.h>

#define NBLK 2048
#define NTHR 256

// Deterministic per-block partials (no atomics on data -> bit-stable across replays)
__device__ double g_part_ce[NBLK];
__device__ double g_part_tp[NBLK];
__device__ double g_part_nc[NBLK];
// wrap counter: atomicInc wraps back to 0 after NBLK arrivals -> replay-safe
__device__ unsigned int g_arrived = 0;

struct Acc { float ce; float tp; int nc; };

__device__ __forceinline__ void process_row(
    float4 lo, float4 hi, int t, const float* __restrict__ s_bw, Acc& a)
{
    const float r15 = 1.0f / 1.5f;
    float l0=lo.x, l1=lo.y, l2=lo.z, l3=lo.w;
    float l4=hi.x, l5=hi.y, l6=hi.z, l7=hi.w;

    // max + argmax (first-max semantics; strict >)
    float m = l0; int am = 0;
    if (l1 > m) { m = l1; am = 1; }
    if (l2 > m) { m = l2; am = 2; }
    if (l3 > m) { m = l3; am = 3; }
    if (l4 > m) { m = l4; am = 4; }
    if (l5 > m) { m = l5; am = 5; }
    if (l6 > m) { m = l6; am = 6; }
    if (l7 > m) { m = l7; am = 7; }

    float d0=l0-m, d1=l1-m, d2=l2-m, d3=l3-m;
    float d4=l4-m, d5=l5-m, d6=l6-m, d7=l7-m;

    // softmax @ T=1 (recall term)
    float e0=__expf(d0), e1=__expf(d1), e2=__expf(d2), e3=__expf(d3);
    float e4=__expf(d4), e5=__expf(d5), e6=__expf(d6), e7=__expf(d7);
    float s1  = ((e0+e1)+(e2+e3)) + ((e4+e5)+(e6+e7));
    float s1c = (e0+e1)+e3;

    // log_softmax @ T=1.5 (CE term)
    float z0=d0*r15, z1=d1*r15, z2=d2*r15, z3=d3*r15;
    float z4=d4*r15, z5=d5*r15, z6=d6*r15, z7=d7*r15;
    float f0=__expf(z0), f1=__expf(z1), f2=__expf(z2), f3=__expf(z3);
    float f4=__expf(z4), f5=__expf(z5), f6=__expf(z6), f7=__expf(z7);
    float s2 = ((f0+f1)+(f2+f3)) + ((f4+f5)+(f6+f7));
    float lse = __logf(s2);

    float zsum = ((z0+z1)+(z2+z3)) + ((z4+z5)+(z6+z7));
    float zcs  = (z0+z1)+z3;

    float zt = z0;
    zt = (t==1) ? z1 : zt;
    zt = (t==2) ? z2 : zt;
    zt = (t==3) ? z3 : zt;
    zt = (t==4) ? z4 : zt;
    zt = (t==5) ? z5 : zt;
    zt = (t==6) ? z6 : zt;
    zt = (t==7) ? z7 : zt;

    float sum_lp = zsum - 8.0f * lse;
    float lp_t   = zt   - lse;
    float lp_c   = zcs  - 3.0f * lse;

    bool ct = (t==0) | (t==1) | (t==3);
    // cancer row:  smooth=0.05 -> A=0.05/8, B=0.95, E=0        (sum=1)
    // benign row:  smooth=0.10 -> (0.0125 + 0.9*onehot + 0.0166667*cancer)/1.05
    float Ac = ct ? 0.00625f : 0.0119047619f;
    float Bc = ct ? 0.95f    : 0.8571428571f;
    float Ec = ct ? 0.0f     : 0.0158730159f;

    float ce = -(Ac * sum_lp + Bc * lp_t + Ec * lp_c);
    ce *= s_bw[t];

    bool pc = (am==0) | (am==1) | (am==3);
    float mult = 1.0f;
    if (ct && !pc)       mult = 3.0f;   // FN_MULT
    if ((t==0) && !pc)   mult = 5.0f;   // MEL_FN_MULT (overrides)
    if (ct && (am != t)) mult *= 2.0f;  // hard mining
    ce *= mult;

    a.ce += ce;
    if (ct) { a.tp += __fdividef(s1c, s1); a.nc++; }
}

__global__ __launch_bounds__(NTHR) void mrl_main(
    const float4* __restrict__ L4,
    const int*    __restrict__ targets,
    const float*  __restrict__ counts,
    float* __restrict__ out,
    int B)
{
    __shared__ float s_bw[8];
    if (threadIdx.x == 0) {
        float w0 = rsqrtf(counts[0] + 1.0f), w1 = rsqrtf(counts[1] + 1.0f);
        float w2 = rsqrtf(counts[2] + 1.0f), w3 = rsqrtf(counts[3] + 1.0f);
        float w4 = rsqrtf(counts[4] + 1.0f), w5 = rsqrtf(counts[5] + 1.0f);
        float w6 = rsqrtf(counts[6] + 1.0f), w7 = rsqrtf(counts[7] + 1.0f);
        float s = ((w0+w1)+(w2+w3)) + ((w4+w5)+(w6+w7));
        float inv = 8.0f / s;
        s_bw[0]=w0*inv; s_bw[1]=w1*inv; s_bw[2]=w2*inv; s_bw[3]=w3*inv;
        s_bw[4]=w4*inv; s_bw[5]=w5*inv; s_bw[6]=w6*inv; s_bw[7]=w7*inv;
    }
    __syncthreads();

    Acc a; a.ce = 0.f; a.tp = 0.f; a.nc = 0;

    const int stride = NBLK * NTHR;
    int r = blockIdx.x * NTHR + threadIdx.x;

    // four rows per iteration: 8 independent float4 loads in flight (MLP 8)
    for (; r + 3 * stride < B; r += 4 * stride) {
        int r1 = r + stride, r2 = r + 2 * stride, r3 = r + 3 * stride;
        const float4* p0 = L4 + ((long long)r  << 1);
        const float4* p1 = L4 + ((long long)r1 << 1);
        const float4* p2 = L4 + ((long long)r2 << 1);
        const float4* p3 = L4 + ((long long)r3 << 1);
        float4 a0 = __ldg(p0),     b0 = __ldg(p0 + 1);
        float4 a1 = __ldg(p1),     b1 = __ldg(p1 + 1);
        float4 a2 = __ldg(p2),     b2 = __ldg(p2 + 1);
        float4 a3 = __ldg(p3),     b3 = __ldg(p3 + 1);
        int t0 = __ldg(targets + r);
        int t1 = __ldg(targets + r1);
        int t2 = __ldg(targets + r2);
        int t3 = __ldg(targets + r3);
        process_row(a0, b0, t0, s_bw, a);
        process_row(a1, b1, t1, s_bw, a);
        process_row(a2, b2, t2, s_bw, a);
        process_row(a3, b3, t3, s_bw, a);
    }
    for (; r < B; r += stride) {
        const float4* p = L4 + ((long long)r << 1);
        float4 lo = __ldg(p);
        float4 hi = __ldg(p + 1);
        int t = __ldg(targets + r);
        process_row(lo, hi, t, s_bw, a);
    }

    float ce_sum = a.ce, tp_sum = a.tp;
    int nc = a.nc;

    // warp reduce
    #pragma unroll
    for (int o = 16; o; o >>= 1) {
        ce_sum += __shfl_down_sync(0xffffffffu, ce_sum, o);
        tp_sum += __shfl_down_sync(0xffffffffu, tp_sum, o);
        nc     += __shfl_down_sync(0xffffffffu, nc,     o);
    }

    __shared__ float sh_ce[NTHR/32], sh_tp[NTHR/32];
    __shared__ int   sh_nc[NTHR/32];
    int wid = threadIdx.x >> 5, lid = threadIdx.x & 31;
    if (lid == 0) { sh_ce[wid] = ce_sum; sh_tp[wid] = tp_sum; sh_nc[wid] = nc; }
    __syncthreads();

    __shared__ bool s_last;
    if (threadIdx.x == 0) {
        double c = 0.0, tpd = 0.0; long long n = 0;
        #pragma unroll
        for (int i = 0; i < NTHR/32; i++) { c += (double)sh_ce[i]; tpd += (double)sh_tp[i]; n += sh_nc[i]; }
        g_part_ce[blockIdx.x] = c;
        g_part_tp[blockIdx.x] = tpd;
        g_part_nc[blockIdx.x] = (double)n;
        __threadfence();
        // wraps to 0 after NBLK arrivals -> counter is 0 again at next replay
        unsigned prev = atomicInc(&g_arrived, NBLK - 1);
        s_last = (prev == NBLK - 1);
    }
    __syncthreads();

    if (s_last) {
        // last-arriving block: deterministic fixed-order final reduction
        __threadfence();  // acquire: make all blocks' partials visible
        __shared__ double sc[NTHR], st[NTHR], sn[NTHR];
        double c = 0.0, t = 0.0, n = 0.0;
        for (int i = threadIdx.x; i < NBLK; i += NTHR) {
            c += __ldcg(&g_part_ce[i]);
            t += __ldcg(&g_part_tp[i]);
            n += __ldcg(&g_part_nc[i]);
        }
        sc[threadIdx.x] = c; st[threadIdx.x] = t; sn[threadIdx.x] = n;
        __syncthreads();
        #pragma unroll
        for (int o = NTHR/2; o; o >>= 1) {
            if (threadIdx.x < o) {
                sc[threadIdx.x] += sc[threadIdx.x + o];
                st[threadIdx.x] += st[threadIdx.x + o];
                sn[threadIdx.x] += sn[threadIdx.x + o];
            }
            __syncthreads();
        }
        if (threadIdx.x == 0) {
            double base_loss = sc[0] / (double)B;
            double soft_recall = st[0] / (sn[0] + 1e-8);
            out[0] = (float)(base_loss + 0.5 * (1.0 - soft_recall));
        }
    }
}

extern "C" void kernel_launch(void* const* d_in, const int* in_sizes, int n_in,
                              void* d_out, int out_size) {
    const float* logits  = (const float*)d_in[0];
    const int*   targets = (const int*)d_in[1];
    const float* counts  = (const float*)d_in[2];
    float* out = (float*)d_out;
    int B = in_sizes[1];   // number of rows (targets element count)

    mrl_main<<<NBLK, NTHR>>>((const float4*)logits, targets, counts, out, B);
}